// round 1
// baseline (speedup 1.0000x reference)
#include <cuda_runtime.h>
#include <math.h>

#define BROWS 16384
#define DCOLS 2048
#define DMASK 2047
#define INV_LOG_D 0.13115409961775f   // 1/log(2048)

// Scratch (no allocations allowed): 5*64KB + 16B = ~320KB
__device__ float g_disp[BROWS];
__device__ float g_tot[BROWS];
__device__ float g_minf[BROWS];
__device__ float g_maxf[BROWS];
__device__ float g_rowc[BROWS];
__device__ float g_scal[4];   // [0]=invM, [1]=gmin(combined), [2]=scale

__device__ __forceinline__ float warp_sum(float v) {
#pragma unroll
    for (int o = 16; o; o >>= 1) v += __shfl_xor_sync(0xffffffffu, v, o);
    return v;
}
__device__ __forceinline__ float warp_min(float v) {
#pragma unroll
    for (int o = 16; o; o >>= 1) v = fminf(v, __shfl_xor_sync(0xffffffffu, v, o));
    return v;
}
__device__ __forceinline__ float warp_max(float v) {
#pragma unroll
    for (int o = 16; o; o >>= 1) v = fmaxf(v, __shfl_xor_sync(0xffffffffu, v, o));
    return v;
}

__device__ __forceinline__ float sigm(float x) {
    return 1.0f / (1.0f + expf(-x));
}

// ---------------------------------------------------------------------------
// Kernel 1: per-row statistics. One block (512 thr) per row, float4 loads.
//   - entropy sum, psi sum / sumsq
//   - circular-gradient sum/sumsq for psi and field (via shared row)
//   - per-row min/max of |field|
// ---------------------------------------------------------------------------
__global__ __launch_bounds__(512) void k_rowstats(
    const float* __restrict__ psi, const float* __restrict__ field)
{
    __shared__ float sp[DCOLS];
    __shared__ float sf[DCOLS];
    __shared__ float red[7][16];
    __shared__ float redmn[16], redmx[16];

    const int row = blockIdx.x;
    const int t = threadIdx.x;
    const size_t base = (size_t)row * DCOLS;

    float4 pv = reinterpret_cast<const float4*>(psi + base)[t];
    float4 fv = reinterpret_cast<const float4*>(field + base)[t];
    reinterpret_cast<float4*>(sp)[t] = pv;
    reinterpret_cast<float4*>(sf)[t] = fv;

    float pe[4] = {pv.x, pv.y, pv.z, pv.w};
    float fe[4] = {fv.x, fv.y, fv.z, fv.w};

    float pl = 0.f, ps = 0.f, ps2 = 0.f;
    float mn = 1e30f, mx = 0.f;
#pragma unroll
    for (int k = 0; k < 4; k++) {
        float p = pe[k];
        pl += p * logf(p + 1e-10f);
        ps += p;
        ps2 += p * p;
        float a = fabsf(fe[k]);
        mn = fminf(mn, a);
        mx = fmaxf(mx, a);
    }
    __syncthreads();

    float gs = 0.f, gs2 = 0.f, hs = 0.f, hs2 = 0.f;
#pragma unroll
    for (int k = 0; k < 4; k++) {
        int j = 4 * t + k;
        int jm = (j - 1) & DMASK;
        int jp = (j + 1) & DMASK;
        float gp = (sp[jp] - sp[jm]) * 0.5f;
        float gf = (sf[jp] - sf[jm]) * 0.5f;
        gs += gp;  gs2 += gp * gp;
        hs += gf;  hs2 += gf * gf;
    }

    // block reduction: 7 sums + min + max
    pl = warp_sum(pl);  ps = warp_sum(ps);  ps2 = warp_sum(ps2);
    gs = warp_sum(gs);  gs2 = warp_sum(gs2);
    hs = warp_sum(hs);  hs2 = warp_sum(hs2);
    mn = warp_min(mn);  mx = warp_max(mx);

    const int wid = t >> 5, lane = t & 31;
    if (lane == 0) {
        red[0][wid] = pl;  red[1][wid] = ps;  red[2][wid] = ps2;
        red[3][wid] = gs;  red[4][wid] = gs2;
        red[5][wid] = hs;  red[6][wid] = hs2;
        redmn[wid] = mn;   redmx[wid] = mx;
    }
    __syncthreads();

    if (t == 0) {
        float a0 = 0.f, a1 = 0.f, a2 = 0.f, a3 = 0.f, a4 = 0.f, a5 = 0.f, a6 = 0.f;
        float amn = 1e30f, amx = 0.f;
#pragma unroll
        for (int i = 0; i < 16; i++) {
            a0 += red[0][i]; a1 += red[1][i]; a2 += red[2][i];
            a3 += red[3][i]; a4 += red[4][i];
            a5 += red[5][i]; a6 += red[6][i];
            amn = fminf(amn, redmn[i]);
            amx = fmaxf(amx, redmx[i]);
        }
        const float n = (float)DCOLS;
        const float inv_nm1 = 1.0f / (n - 1.0f);

        float mean = a1 / n;
        float var = fmaxf((a2 - a1 * mean) * inv_nm1, 0.f);   // unbiased
        float pstd = sqrtf(var);
        float norm_ent = (-a0) * INV_LOG_D;
        float disp = fminf(fmaxf(0.7f * norm_ent + 0.3f * pstd, 0.f), 1.f);

        float gmean = a3 / n;
        float gvar = fmaxf((a4 - a3 * gmean) * inv_nm1, 0.f);
        float hmean = a5 / n;
        float hvar = fmaxf((a6 - a5 * hmean) * inv_nm1, 0.f);
        float tot = sqrtf(gvar + hvar);   // sqrt(pc^2 + fc^2)

        g_disp[row] = disp;
        g_tot[row]  = tot;
        g_minf[row] = amn;
        g_maxf[row] = amx;
    }
}

// ---------------------------------------------------------------------------
// Kernel 2: single block. Global M = max|field|, maxtot; per-row constant;
// global min/max of combined via sigmoid monotonicity on per-row min/max |f|.
// ---------------------------------------------------------------------------
__global__ __launch_bounds__(1024) void k_global(const float* __restrict__ w)
{
    __shared__ float s1[32], s2[32];
    __shared__ float sM, sT;
    const int t = threadIdx.x;
    const int wid = t >> 5, lane = t & 31;

    float m1 = 0.f, m2 = 0.f;
    for (int i = t; i < BROWS; i += 1024) {
        m1 = fmaxf(m1, g_maxf[i]);
        m2 = fmaxf(m2, g_tot[i]);
    }
    m1 = warp_max(m1);
    m2 = warp_max(m2);
    if (lane == 0) { s1[wid] = m1; s2[wid] = m2; }
    __syncthreads();
    if (t == 0) {
        float M = 0.f, T = 0.f;
#pragma unroll
        for (int i = 0; i < 32; i++) { M = fmaxf(M, s1[i]); T = fmaxf(T, s2[i]); }
        sM = M; sT = T;
    }
    __syncthreads();

    const float invM = 1.0f / (sM + 1e-10f);
    const float invT = 1.0f / (sT + 1e-10f);
    const float w0 = w[0], w1 = w[1], w2 = w[2], w3 = w[3];

    float cmn = 1e30f, cmx = -1e30f;
    for (int i = t; i < BROWS; i += 1024) {
        float comp = fminf(fmaxf(g_tot[i] * invT, 0.f), 1.f);
        float rc = w0 * g_disp[i] + w2 * comp + w3 * 0.5f;
        g_rowc[i] = rc;
        // same expression as kernel 3 for bitwise-consistent extremes
        float ffa = sigm(5.0f * (g_minf[i] * invM - 0.5f));
        float ffb = sigm(5.0f * (g_maxf[i] * invM - 0.5f));
        float lo = (w1 >= 0.f) ? ffa : ffb;
        float hi = (w1 >= 0.f) ? ffb : ffa;
        cmn = fminf(cmn, rc + w1 * lo);
        cmx = fmaxf(cmx, rc + w1 * hi);
    }
    cmn = warp_min(cmn);
    cmx = warp_max(cmx);
    if (lane == 0) { s1[wid] = cmn; s2[wid] = cmx; }
    __syncthreads();
    if (t == 0) {
        float gmn = 1e30f, gmx = -1e30f;
#pragma unroll
        for (int i = 0; i < 32; i++) { gmn = fminf(gmn, s1[i]); gmx = fmaxf(gmx, s2[i]); }
        g_scal[0] = invM;
        g_scal[1] = gmn;
        g_scal[2] = 0.099f / (gmx - gmn + 1e-10f);   // (D_MAX-D_MIN)/range
    }
}

// ---------------------------------------------------------------------------
// Kernel 3: finalize. field -> field_factor -> combined -> dc -> 3-tap smooth.
// One block per row; smoothing via shared dc row (circular).
// ---------------------------------------------------------------------------
__global__ __launch_bounds__(512) void k_final(
    const float* __restrict__ field, const float* __restrict__ w,
    float* __restrict__ out)
{
    __shared__ float dc[DCOLS];
    const int row = blockIdx.x;
    const int t = threadIdx.x;
    const size_t base = (size_t)row * DCOLS;

    const float invM = g_scal[0];
    const float gmn  = g_scal[1];
    const float sc   = g_scal[2];
    const float rc   = g_rowc[row];
    const float w1   = w[1];

    float4 fv = reinterpret_cast<const float4*>(field + base)[t];
    float fe[4] = {fv.x, fv.y, fv.z, fv.w};
    float de[4];
#pragma unroll
    for (int k = 0; k < 4; k++) {
        float a = fabsf(fe[k]);
        float ff = sigm(5.0f * (a * invM - 0.5f));
        float c = rc + w1 * ff;
        de[k] = 0.001f + (c - gmn) * sc;
    }
    reinterpret_cast<float4*>(dc)[t] = make_float4(de[0], de[1], de[2], de[3]);
    __syncthreads();

    float oe[4];
#pragma unroll
    for (int k = 0; k < 4; k++) {
        int j = 4 * t + k;
        oe[k] = 0.25f * dc[(j - 1) & DMASK] + 0.5f * dc[j] + 0.25f * dc[(j + 1) & DMASK];
    }
    reinterpret_cast<float4*>(out + base)[t] = make_float4(oe[0], oe[1], oe[2], oe[3]);
}

// ---------------------------------------------------------------------------
extern "C" void kernel_launch(void* const* d_in, const int* in_sizes, int n_in,
                              void* d_out, int out_size)
{
    const float* psi   = (const float*)d_in[0];
    const float* field = (const float*)d_in[1];
    const float* w     = (const float*)d_in[2];
    float* out = (float*)d_out;

    k_rowstats<<<BROWS, 512>>>(psi, field);
    k_global<<<1, 1024>>>(w);
    k_final<<<BROWS, 512>>>(field, w, out);
}

// round 5
// speedup vs baseline: 1.1784x; 1.1784x over previous
#include <cuda_runtime.h>
#include <math.h>

#define BROWS 16384
#define DCOLS 2048
#define INV_LOG_D 0.13115409961775f   // 1/log(2048)

// Scratch (no allocations allowed)
__device__ float g_disp[BROWS];
__device__ float g_tot[BROWS];
__device__ float g_minf[BROWS];
__device__ float g_maxf[BROWS];
__device__ float g_rowc[BROWS];
__device__ float g_scal[4];   // [0]=invM, [1]=gmin(combined), [2]=scale

__device__ __forceinline__ float warp_sum(float v) {
#pragma unroll
    for (int o = 16; o; o >>= 1) v += __shfl_xor_sync(0xffffffffu, v, o);
    return v;
}
__device__ __forceinline__ float warp_min(float v) {
#pragma unroll
    for (int o = 16; o; o >>= 1) v = fminf(v, __shfl_xor_sync(0xffffffffu, v, o));
    return v;
}
__device__ __forceinline__ float warp_max(float v) {
#pragma unroll
    for (int o = 16; o; o >>= 1) v = fmaxf(v, __shfl_xor_sync(0xffffffffu, v, o));
    return v;
}

// fast sigmoid — MUST be identical in k_global and k_final (min/max consistency)
__device__ __forceinline__ float sigm(float x) {
    return 1.0f / (1.0f + __expf(-x));
}

// ---------------------------------------------------------------------------
// Kernel 1: per-row statistics. One block (512 thr) per row, float4 loads.
// Register-resident gradients; only thread-edge elements go through smem.
// Gradient mean is exactly 0 (circular telescoping) -> var = sum(g^2)/(n-1).
// ---------------------------------------------------------------------------
__global__ __launch_bounds__(512) void k_rowstats(
    const float* __restrict__ psi, const float* __restrict__ field)
{
    __shared__ float spR[512], spL[512];   // psi edges: e3 (right), e0 (left)
    __shared__ float sfR[512], sfL[512];   // field edges
    __shared__ float red[5][16];
    __shared__ float redmn[16], redmx[16];

    const int row = blockIdx.x;
    const int t = threadIdx.x;
    const size_t base = (size_t)row * DCOLS;

    float4 pv = reinterpret_cast<const float4*>(psi + base)[t];
    float4 fv = reinterpret_cast<const float4*>(field + base)[t];

    spL[t] = pv.x;  spR[t] = pv.w;
    sfL[t] = fv.x;  sfR[t] = fv.w;

    // elementwise stats (no neighbors needed)
    float pl, ps, ps2, mn, mx;
    {
        float p0 = pv.x, p1 = pv.y, p2 = pv.z, p3 = pv.w;
        pl = p0 * __logf(p0 + 1e-10f) + p1 * __logf(p1 + 1e-10f)
           + p2 * __logf(p2 + 1e-10f) + p3 * __logf(p3 + 1e-10f);
        ps  = (p0 + p1) + (p2 + p3);
        ps2 = (p0 * p0 + p1 * p1) + (p2 * p2 + p3 * p3);
        float a0 = fabsf(fv.x), a1 = fabsf(fv.y), a2 = fabsf(fv.z), a3 = fabsf(fv.w);
        mn = fminf(fminf(a0, a1), fminf(a2, a3));
        mx = fmaxf(fmaxf(a0, a1), fmaxf(a2, a3));
    }
    __syncthreads();

    // neighbor edge elements (circular over 512 threads == full row)
    const int tm = (t - 1) & 511;
    const int tp = (t + 1) & 511;
    float p_prev = spR[tm], p_next = spL[tp];
    float f_prev = sfR[tm], f_next = sfL[tp];

    float gs2, hs2;
    {
        float g0 = pv.y - p_prev;
        float g1 = pv.z - pv.x;
        float g2 = pv.w - pv.y;
        float g3 = p_next - pv.z;
        gs2 = 0.25f * ((g0 * g0 + g1 * g1) + (g2 * g2 + g3 * g3));
        float h0 = fv.y - f_prev;
        float h1 = fv.z - fv.x;
        float h2 = fv.w - fv.y;
        float h3 = f_next - fv.z;
        hs2 = 0.25f * ((h0 * h0 + h1 * h1) + (h2 * h2 + h3 * h3));
    }

    // block reduction: 5 sums + min + max
    pl = warp_sum(pl);  ps = warp_sum(ps);  ps2 = warp_sum(ps2);
    gs2 = warp_sum(gs2);  hs2 = warp_sum(hs2);
    mn = warp_min(mn);  mx = warp_max(mx);

    const int wid = t >> 5, lane = t & 31;
    if (lane == 0) {
        red[0][wid] = pl;  red[1][wid] = ps;  red[2][wid] = ps2;
        red[3][wid] = gs2; red[4][wid] = hs2;
        redmn[wid] = mn;   redmx[wid] = mx;
    }
    __syncthreads();

    if (t == 0) {
        float a0 = 0.f, a1 = 0.f, a2 = 0.f, a3 = 0.f, a4 = 0.f;
        float amn = 1e30f, amx = 0.f;
#pragma unroll
        for (int i = 0; i < 16; i++) {
            a0 += red[0][i]; a1 += red[1][i]; a2 += red[2][i];
            a3 += red[3][i]; a4 += red[4][i];
            amn = fminf(amn, redmn[i]);
            amx = fmaxf(amx, redmx[i]);
        }
        const float n = (float)DCOLS;
        const float inv_nm1 = 1.0f / (n - 1.0f);

        float mean = a1 / n;
        float var = fmaxf((a2 - a1 * mean) * inv_nm1, 0.f);   // unbiased
        float pstd = sqrtf(var);
        float norm_ent = (-a0) * INV_LOG_D;
        float disp = fminf(fmaxf(0.7f * norm_ent + 0.3f * pstd, 0.f), 1.f);

        // circular gradient has exactly zero mean -> var = sum(g^2)/(n-1)
        float gvar = a3 * inv_nm1;
        float hvar = a4 * inv_nm1;
        float tot = sqrtf(gvar + hvar);

        g_disp[row] = disp;
        g_tot[row]  = tot;
        g_minf[row] = amn;
        g_maxf[row] = amx;
    }
}

// ---------------------------------------------------------------------------
// Kernel 2: single block. Global M = max|field|, maxtot; per-row constant;
// global min/max of combined via sigmoid monotonicity on per-row min/max |f|.
// ---------------------------------------------------------------------------
__global__ __launch_bounds__(1024) void k_global(const float* __restrict__ w)
{
    __shared__ float s1[32], s2[32];
    __shared__ float sM, sT;
    const int t = threadIdx.x;
    const int wid = t >> 5, lane = t & 31;

    float m1 = 0.f, m2 = 0.f;
    for (int i = t; i < BROWS; i += 1024) {
        m1 = fmaxf(m1, g_maxf[i]);
        m2 = fmaxf(m2, g_tot[i]);
    }
    m1 = warp_max(m1);
    m2 = warp_max(m2);
    if (lane == 0) { s1[wid] = m1; s2[wid] = m2; }
    __syncthreads();
    if (t == 0) {
        float M = 0.f, T = 0.f;
#pragma unroll
        for (int i = 0; i < 32; i++) { M = fmaxf(M, s1[i]); T = fmaxf(T, s2[i]); }
        sM = M; sT = T;
    }
    __syncthreads();

    const float invM = 1.0f / (sM + 1e-10f);
    const float invT = 1.0f / (sT + 1e-10f);
    const float w0 = w[0], w1 = w[1], w2 = w[2], w3 = w[3];

    float cmn = 1e30f, cmx = -1e30f;
    for (int i = t; i < BROWS; i += 1024) {
        float comp = fminf(fmaxf(g_tot[i] * invT, 0.f), 1.f);
        float rc = w0 * g_disp[i] + w2 * comp + w3 * 0.5f;
        g_rowc[i] = rc;
        // same expression as kernel 3 for consistent extremes
        float ffa = sigm(5.0f * (g_minf[i] * invM - 0.5f));
        float ffb = sigm(5.0f * (g_maxf[i] * invM - 0.5f));
        float lo = (w1 >= 0.f) ? ffa : ffb;
        float hi = (w1 >= 0.f) ? ffb : ffa;
        cmn = fminf(cmn, rc + w1 * lo);
        cmx = fmaxf(cmx, rc + w1 * hi);
    }
    cmn = warp_min(cmn);
    cmx = warp_max(cmx);
    if (lane == 0) { s1[wid] = cmn; s2[wid] = cmx; }
    __syncthreads();
    if (t == 0) {
        float gmn = 1e30f, gmx = -1e30f;
#pragma unroll
        for (int i = 0; i < 32; i++) { gmn = fminf(gmn, s1[i]); gmx = fmaxf(gmx, s2[i]); }
        g_scal[0] = invM;
        g_scal[1] = gmn;
        g_scal[2] = 0.099f / (gmx - gmn + 1e-10f);   // (D_MAX-D_MIN)/range
    }
}

// ---------------------------------------------------------------------------
// Kernel 3: finalize. field -> field_factor -> combined -> dc -> 3-tap smooth.
// One block per row; only thread-edge dc values cross threads (2KB smem).
// ---------------------------------------------------------------------------
__global__ __launch_bounds__(512) void k_final(
    const float* __restrict__ field, const float* __restrict__ w,
    float* __restrict__ out)
{
    __shared__ float sdL[512], sdR[512];
    const int row = blockIdx.x;
    const int t = threadIdx.x;
    const size_t base = (size_t)row * DCOLS;

    const float invM = g_scal[0];
    const float gmn  = g_scal[1];
    const float sc   = g_scal[2];
    const float rc   = g_rowc[row];
    const float w1   = w[1];

    float4 fv = reinterpret_cast<const float4*>(field + base)[t];
    float de[4];
    {
        float fe[4] = {fv.x, fv.y, fv.z, fv.w};
#pragma unroll
        for (int k = 0; k < 4; k++) {
            float a = fabsf(fe[k]);
            float ff = sigm(5.0f * (a * invM - 0.5f));
            float c = rc + w1 * ff;
            de[k] = 0.001f + (c - gmn) * sc;
        }
    }
    sdL[t] = de[0];
    sdR[t] = de[3];
    __syncthreads();

    const float d_prev = sdR[(t - 1) & 511];
    const float d_next = sdL[(t + 1) & 511];

    float4 ov;
    ov.x = 0.25f * d_prev + 0.5f * de[0] + 0.25f * de[1];
    ov.y = 0.25f * de[0] + 0.5f * de[1] + 0.25f * de[2];
    ov.z = 0.25f * de[1] + 0.5f * de[2] + 0.25f * de[3];
    ov.w = 0.25f * de[2] + 0.5f * de[3] + 0.25f * d_next;
    reinterpret_cast<float4*>(out + base)[t] = ov;
}

// ---------------------------------------------------------------------------
extern "C" void kernel_launch(void* const* d_in, const int* in_sizes, int n_in,
                              void* d_out, int out_size)
{
    const float* psi   = (const float*)d_in[0];
    const float* field = (const float*)d_in[1];
    const float* w     = (const float*)d_in[2];
    float* out = (float*)d_out;

    k_rowstats<<<BROWS, 512>>>(psi, field);
    k_global<<<1, 1024>>>(w);
    k_final<<<BROWS, 512>>>(field, w, out);
}

// round 6
// speedup vs baseline: 1.6550x; 1.4044x over previous
#include <cuda_runtime.h>
#include <math.h>

#define BROWS 16384
#define DCOLS 2048
#define INV_LOG_D 0.13115409961775f   // 1/log(2048)

// Scratch (no allocations allowed)
__device__ float g_disp[BROWS];
__device__ float g_tot[BROWS];
__device__ float g_minf[BROWS];
__device__ float g_maxf[BROWS];
__device__ float g_rowc[BROWS];
__device__ float g_scal[4];   // [0]=invM, [1]=gmin(combined), [2]=scale

__device__ __forceinline__ float warp_sum(float v) {
#pragma unroll
    for (int o = 16; o; o >>= 1) v += __shfl_xor_sync(0xffffffffu, v, o);
    return v;
}
__device__ __forceinline__ float warp_min(float v) {
#pragma unroll
    for (int o = 16; o; o >>= 1) v = fminf(v, __shfl_xor_sync(0xffffffffu, v, o));
    return v;
}
__device__ __forceinline__ float warp_max(float v) {
#pragma unroll
    for (int o = 16; o; o >>= 1) v = fmaxf(v, __shfl_xor_sync(0xffffffffu, v, o));
    return v;
}

// fast sigmoid — MUST be identical in k_global and k_final (min/max consistency)
__device__ __forceinline__ float sigm(float x) {
    return 1.0f / (1.0f + __expf(-x));
}

// ---------------------------------------------------------------------------
// Kernel 1: per-row statistics. 256 threads/row; each thread owns two
// 4-element chunks (float4 at t and t+256) -> 4 independent coalesced
// LDG.128 front-batched (MLP=4). Edge exchange over 512 chunk slots.
// Circular gradient mean is exactly 0 -> var = sum(g^2)/(n-1).
// ---------------------------------------------------------------------------
__global__ __launch_bounds__(256) void k_rowstats(
    const float* __restrict__ psi, const float* __restrict__ field)
{
    __shared__ float spL[512], spR[512];   // psi chunk edges (first, last elem)
    __shared__ float sfL[512], sfR[512];   // field chunk edges
    __shared__ float red[5][8];
    __shared__ float redmn[8], redmx[8];

    const int row = blockIdx.x;
    const int t = threadIdx.x;
    const size_t base = (size_t)row * DCOLS;
    const float4* P = reinterpret_cast<const float4*>(psi + base);
    const float4* F = reinterpret_cast<const float4*>(field + base);

    // 4 independent coalesced loads, front-batched
    float4 pa = P[t];
    float4 pb = P[t + 256];
    float4 fa = F[t];
    float4 fb = F[t + 256];

    // chunk ids: ca = t, cb = 256 + t (512 chunks of 4 elems circular)
    spL[t] = pa.x;        spR[t] = pa.w;
    spL[256 + t] = pb.x;  spR[256 + t] = pb.w;
    sfL[t] = fa.x;        sfR[t] = fa.w;
    sfL[256 + t] = fb.x;  sfR[256 + t] = fb.w;

    // elementwise stats over 8 psi elems / 8 field elems
    float pl, ps, ps2, mn, mx;
    {
        float p0 = pa.x, p1 = pa.y, p2 = pa.z, p3 = pa.w;
        float p4 = pb.x, p5 = pb.y, p6 = pb.z, p7 = pb.w;
        pl = p0 * __logf(p0 + 1e-10f) + p1 * __logf(p1 + 1e-10f)
           + p2 * __logf(p2 + 1e-10f) + p3 * __logf(p3 + 1e-10f)
           + p4 * __logf(p4 + 1e-10f) + p5 * __logf(p5 + 1e-10f)
           + p6 * __logf(p6 + 1e-10f) + p7 * __logf(p7 + 1e-10f);
        ps  = ((p0 + p1) + (p2 + p3)) + ((p4 + p5) + (p6 + p7));
        ps2 = ((p0 * p0 + p1 * p1) + (p2 * p2 + p3 * p3))
            + ((p4 * p4 + p5 * p5) + (p6 * p6 + p7 * p7));
        float a0 = fabsf(fa.x), a1 = fabsf(fa.y), a2 = fabsf(fa.z), a3 = fabsf(fa.w);
        float a4 = fabsf(fb.x), a5 = fabsf(fb.y), a6 = fabsf(fb.z), a7 = fabsf(fb.w);
        mn = fminf(fminf(fminf(a0, a1), fminf(a2, a3)),
                   fminf(fminf(a4, a5), fminf(a6, a7)));
        mx = fmaxf(fmaxf(fmaxf(a0, a1), fmaxf(a2, a3)),
                   fmaxf(fmaxf(a4, a5), fmaxf(a6, a7)));
    }
    __syncthreads();

    // gradients: chunk ca = t, chunk cb = 256 + t
    float gs2, hs2;
    {
        const int ca = t, cb = 256 + t;
        float pA_prev = spR[(ca - 1) & 511], pA_next = spL[(ca + 1) & 511];
        float pB_prev = spR[(cb - 1) & 511], pB_next = spL[(cb + 1) & 511];
        float fA_prev = sfR[(ca - 1) & 511], fA_next = sfL[(ca + 1) & 511];
        float fB_prev = sfR[(cb - 1) & 511], fB_next = sfL[(cb + 1) & 511];

        float g0 = pa.y - pA_prev;
        float g1 = pa.z - pa.x;
        float g2 = pa.w - pa.y;
        float g3 = pA_next - pa.z;
        float g4 = pb.y - pB_prev;
        float g5 = pb.z - pb.x;
        float g6 = pb.w - pb.y;
        float g7 = pB_next - pb.z;
        gs2 = 0.25f * (((g0 * g0 + g1 * g1) + (g2 * g2 + g3 * g3))
                     + ((g4 * g4 + g5 * g5) + (g6 * g6 + g7 * g7)));

        float h0 = fa.y - fA_prev;
        float h1 = fa.z - fa.x;
        float h2 = fa.w - fa.y;
        float h3 = fA_next - fa.z;
        float h4 = fb.y - fB_prev;
        float h5 = fb.z - fb.x;
        float h6 = fb.w - fb.y;
        float h7 = fB_next - fb.z;
        hs2 = 0.25f * (((h0 * h0 + h1 * h1) + (h2 * h2 + h3 * h3))
                     + ((h4 * h4 + h5 * h5) + (h6 * h6 + h7 * h7)));
    }

    // block reduction: 5 sums + min + max (8 warps)
    pl = warp_sum(pl);  ps = warp_sum(ps);  ps2 = warp_sum(ps2);
    gs2 = warp_sum(gs2);  hs2 = warp_sum(hs2);
    mn = warp_min(mn);  mx = warp_max(mx);

    const int wid = t >> 5, lane = t & 31;
    if (lane == 0) {
        red[0][wid] = pl;  red[1][wid] = ps;  red[2][wid] = ps2;
        red[3][wid] = gs2; red[4][wid] = hs2;
        redmn[wid] = mn;   redmx[wid] = mx;
    }
    __syncthreads();

    if (t == 0) {
        float a0 = 0.f, a1 = 0.f, a2 = 0.f, a3 = 0.f, a4 = 0.f;
        float amn = 1e30f, amx = 0.f;
#pragma unroll
        for (int i = 0; i < 8; i++) {
            a0 += red[0][i]; a1 += red[1][i]; a2 += red[2][i];
            a3 += red[3][i]; a4 += red[4][i];
            amn = fminf(amn, redmn[i]);
            amx = fmaxf(amx, redmx[i]);
        }
        const float n = (float)DCOLS;
        const float inv_nm1 = 1.0f / (n - 1.0f);

        float mean = a1 / n;
        float var = fmaxf((a2 - a1 * mean) * inv_nm1, 0.f);   // unbiased
        float pstd = sqrtf(var);
        float norm_ent = (-a0) * INV_LOG_D;
        float disp = fminf(fmaxf(0.7f * norm_ent + 0.3f * pstd, 0.f), 1.f);

        // circular gradient has exactly zero mean -> var = sum(g^2)/(n-1)
        float gvar = a3 * inv_nm1;
        float hvar = a4 * inv_nm1;
        float tot = sqrtf(gvar + hvar);

        g_disp[row] = disp;
        g_tot[row]  = tot;
        g_minf[row] = amn;
        g_maxf[row] = amx;
    }
}

// ---------------------------------------------------------------------------
// Kernel 2: single block. Global M = max|field|, maxtot; per-row constant;
// global min/max of combined via sigmoid monotonicity on per-row min/max |f|.
// ---------------------------------------------------------------------------
__global__ __launch_bounds__(1024) void k_global(const float* __restrict__ w)
{
    __shared__ float s1[32], s2[32];
    __shared__ float sM, sT;
    const int t = threadIdx.x;
    const int wid = t >> 5, lane = t & 31;

    float m1 = 0.f, m2 = 0.f;
    for (int i = t; i < BROWS; i += 1024) {
        m1 = fmaxf(m1, g_maxf[i]);
        m2 = fmaxf(m2, g_tot[i]);
    }
    m1 = warp_max(m1);
    m2 = warp_max(m2);
    if (lane == 0) { s1[wid] = m1; s2[wid] = m2; }
    __syncthreads();
    if (t == 0) {
        float M = 0.f, T = 0.f;
#pragma unroll
        for (int i = 0; i < 32; i++) { M = fmaxf(M, s1[i]); T = fmaxf(T, s2[i]); }
        sM = M; sT = T;
    }
    __syncthreads();

    const float invM = 1.0f / (sM + 1e-10f);
    const float invT = 1.0f / (sT + 1e-10f);
    const float w0 = w[0], w1 = w[1], w2 = w[2], w3 = w[3];

    float cmn = 1e30f, cmx = -1e30f;
    for (int i = t; i < BROWS; i += 1024) {
        float comp = fminf(fmaxf(g_tot[i] * invT, 0.f), 1.f);
        float rc = w0 * g_disp[i] + w2 * comp + w3 * 0.5f;
        g_rowc[i] = rc;
        // same expression as kernel 3 for consistent extremes
        float ffa = sigm(5.0f * (g_minf[i] * invM - 0.5f));
        float ffb = sigm(5.0f * (g_maxf[i] * invM - 0.5f));
        float lo = (w1 >= 0.f) ? ffa : ffb;
        float hi = (w1 >= 0.f) ? ffb : ffa;
        cmn = fminf(cmn, rc + w1 * lo);
        cmx = fmaxf(cmx, rc + w1 * hi);
    }
    cmn = warp_min(cmn);
    cmx = warp_max(cmx);
    if (lane == 0) { s1[wid] = cmn; s2[wid] = cmx; }
    __syncthreads();
    if (t == 0) {
        float gmn = 1e30f, gmx = -1e30f;
#pragma unroll
        for (int i = 0; i < 32; i++) { gmn = fminf(gmn, s1[i]); gmx = fmaxf(gmx, s2[i]); }
        g_scal[0] = invM;
        g_scal[1] = gmn;
        g_scal[2] = 0.099f / (gmx - gmn + 1e-10f);   // (D_MAX-D_MIN)/range
    }
}

// ---------------------------------------------------------------------------
// Kernel 3: finalize. 128 threads/row; each thread owns four 4-element
// chunks (float4 at t + 128k) -> 4 independent coalesced LDG.128 (MLP=4).
// 3-tap circular smoothing via 512-slot chunk-edge exchange.
// ---------------------------------------------------------------------------
__global__ __launch_bounds__(128) void k_final(
    const float* __restrict__ field, const float* __restrict__ w,
    float* __restrict__ out)
{
    __shared__ float sdL[512], sdR[512];
    const int row = blockIdx.x;
    const int t = threadIdx.x;
    const size_t base = (size_t)row * DCOLS;
    const float4* F = reinterpret_cast<const float4*>(field + base);

    const float invM = g_scal[0];
    const float gmn  = g_scal[1];
    const float sc   = g_scal[2];
    const float rc   = g_rowc[row];
    const float w1   = w[1];

    // 4 independent coalesced loads, front-batched
    float4 v0 = F[t];
    float4 v1 = F[t + 128];
    float4 v2 = F[t + 256];
    float4 v3 = F[t + 384];

    float de[16];
    {
        float fe[16] = {v0.x, v0.y, v0.z, v0.w,  v1.x, v1.y, v1.z, v1.w,
                        v2.x, v2.y, v2.z, v2.w,  v3.x, v3.y, v3.z, v3.w};
#pragma unroll
        for (int k = 0; k < 16; k++) {
            float a = fabsf(fe[k]);
            float ff = sigm(5.0f * (a * invM - 0.5f));
            float c = rc + w1 * ff;
            de[k] = 0.001f + (c - gmn) * sc;
        }
    }
    // chunk c = t + 128*k owns de[4k..4k+4)
#pragma unroll
    for (int k = 0; k < 4; k++) {
        sdL[t + 128 * k] = de[4 * k];
        sdR[t + 128 * k] = de[4 * k + 3];
    }
    __syncthreads();

    float4* O = reinterpret_cast<float4*>(out + base);
#pragma unroll
    for (int k = 0; k < 4; k++) {
        const int c = t + 128 * k;
        const float d_prev = sdR[(c - 1) & 511];
        const float d_next = sdL[(c + 1) & 511];
        const float e0 = de[4 * k], e1 = de[4 * k + 1];
        const float e2 = de[4 * k + 2], e3 = de[4 * k + 3];
        float4 ov;
        ov.x = 0.25f * d_prev + 0.5f * e0 + 0.25f * e1;
        ov.y = 0.25f * e0 + 0.5f * e1 + 0.25f * e2;
        ov.z = 0.25f * e1 + 0.5f * e2 + 0.25f * e3;
        ov.w = 0.25f * e2 + 0.5f * e3 + 0.25f * d_next;
        O[c] = ov;
    }
}

// ---------------------------------------------------------------------------
extern "C" void kernel_launch(void* const* d_in, const int* in_sizes, int n_in,
                              void* d_out, int out_size)
{
    const float* psi   = (const float*)d_in[0];
    const float* field = (const float*)d_in[1];
    const float* w     = (const float*)d_in[2];
    float* out = (float*)d_out;

    k_rowstats<<<BROWS, 256>>>(psi, field);
    k_global<<<1, 1024>>>(w);
    k_final<<<BROWS, 128>>>(field, w, out);
}